// round 6
// baseline (speedup 1.0000x reference)
#include <cuda_runtime.h>
#include <cuda_bf16.h>
#include <mma.h>
#include <cstdint>

using namespace nvcuda;

#define MAX_NODES 100032
#define MAX_EDGES 700000
#define D 128
#define D4 (D / 4)

// CSR scratch (rebuilt every replay; deterministic work)
__device__ int g_deg[MAX_NODES];
__device__ int g_rowstart[MAX_NODES];
__device__ int g_cursor[MAX_NODES];
__device__ int g_bsum[256];
__device__ int g_adj[2 * MAX_EDGES];

// ===========================================================================
// CSR build kernels
// ===========================================================================
__global__ void zero_deg_kernel(int n) {
    int i = blockIdx.x * blockDim.x + threadIdx.x;
    if (i < n) g_deg[i] = 0;
}

__global__ void hist_kernel(const int* __restrict__ ra, const int* __restrict__ rb, int n_edges) {
    int e = blockIdx.x * blockDim.x + threadIdx.x;
    if (e >= n_edges) return;
    atomicAdd(&g_deg[ra[e]], 1);
    atomicAdd(&g_deg[rb[e]], 1);
}

// block-wise exclusive scan of g_deg -> g_rowstart (local), block totals -> g_bsum
__global__ void scan_block_kernel(int n) {
    __shared__ int wsum[32];
    int i = blockIdx.x * 1024 + threadIdx.x;
    int lane = threadIdx.x & 31, w = threadIdx.x >> 5;
    int v = (i < n) ? g_deg[i] : 0;
    int s = v;
    #pragma unroll
    for (int o = 1; o < 32; o <<= 1) {
        int t = __shfl_up_sync(0xFFFFFFFFu, s, o);
        if (lane >= o) s += t;
    }
    if (lane == 31) wsum[w] = s;
    __syncthreads();
    if (threadIdx.x < 32) {
        int t = wsum[threadIdx.x];
        int sc = t;
        #pragma unroll
        for (int o = 1; o < 32; o <<= 1) {
            int u = __shfl_up_sync(0xFFFFFFFFu, sc, o);
            if (lane >= o) sc += u;
        }
        wsum[threadIdx.x] = sc - t;                      // exclusive warp offsets
        if (threadIdx.x == 31) g_bsum[blockIdx.x] = sc;  // block total
    }
    __syncthreads();
    if (i < n) g_rowstart[i] = (s - v) + wsum[w];
}

__global__ void scan_top_kernel(int nb) {
    __shared__ int sm[256];
    int t = threadIdx.x;
    if (t < nb) sm[t] = g_bsum[t];
    __syncthreads();
    if (t == 0) {
        int run = 0;
        for (int j = 0; j < nb; ++j) { int x = sm[j]; sm[j] = run; run += x; }
    }
    __syncthreads();
    if (t < nb) g_bsum[t] = sm[t];
}

__global__ void scan_add_kernel(int n) {
    int i = blockIdx.x * 1024 + threadIdx.x;
    if (i < n) {
        int rs = g_rowstart[i] + g_bsum[blockIdx.x];
        g_rowstart[i] = rs;
        g_cursor[i] = rs;
    }
}

__global__ void fill_adj_kernel(const int* __restrict__ ra, const int* __restrict__ rb, int n_edges) {
    int e = blockIdx.x * blockDim.x + threadIdx.x;
    if (e >= n_edges) return;
    int a = ra[e], b = rb[e];
    int p = atomicAdd(&g_cursor[a], 1);
    g_adj[p] = b;
    int q = atomicAdd(&g_cursor[b], 1);
    g_adj[q] = a;
}

// ===========================================================================
// Fused kernel: CSR pull-gather (agg = X + sum of neighbors) -> bf16x3 split
// -> GEMM1 (relu) -> GEMM2 -> out.  CTA = 128 rows, 256 threads / 8 warps.
// ===========================================================================
#define LDA 136   // bf16 leading dim (padded)
#define LDH 132   // f32 leading dim (padded)

#define SM_BH  0
#define SM_BO  512
#define SM_AHI 1024
#define SM_ALO (SM_AHI + 128 * LDA * 2)
#define SM_WHI (SM_ALO + 128 * LDA * 2)
#define SM_WLO (SM_WHI + 128 * LDA * 2)
#define SM_HF  (SM_WLO + 128 * LDA * 2)
#define SM_TOTAL (SM_HF + 128 * LDH * 4)   // 207872 bytes

__device__ __forceinline__ void split2(float x, __nv_bfloat16& hi, __nv_bfloat16& lo) {
    hi = __float2bfloat16_rn(x);
    lo = __float2bfloat16_rn(x - __bfloat162float(hi));
}

__global__ __launch_bounds__(256, 1)
void fused_gather_wmma_kernel(const float4* __restrict__ X4,
                              const float* __restrict__ Wh, const float* __restrict__ bh,
                              const float* __restrict__ Wo, const float* __restrict__ bo,
                              float* __restrict__ out, int n_nodes) {
    extern __shared__ char smem[];
    float*          bh_s = (float*)(smem + SM_BH);
    float*          bo_s = (float*)(smem + SM_BO);
    __nv_bfloat16*  Ahi  = (__nv_bfloat16*)(smem + SM_AHI);
    __nv_bfloat16*  Alo  = (__nv_bfloat16*)(smem + SM_ALO);
    __nv_bfloat16*  Whi  = (__nv_bfloat16*)(smem + SM_WHI);
    __nv_bfloat16*  Wlo  = (__nv_bfloat16*)(smem + SM_WLO);
    float*          Hf   = (float*)(smem + SM_HF);

    const int tid  = threadIdx.x;
    const int wid  = tid >> 5;
    const int lane = tid & 31;
    const int row0 = blockIdx.x * 128;

    if (tid < 128) bh_s[tid] = bh[tid];
    else           bo_s[tid - 128] = bo[tid - 128];

    // --- stage Wh (hi/lo) while gather warms up ---
    {
        const float4* W4 = (const float4*)Wh;
        #pragma unroll
        for (int it = 0; it < 16; ++it) {
            int i = tid + it * 256;
            int k = i >> 5, c = (i & 31) * 4;
            float4 v = W4[i];
            __nv_bfloat16 h0, l0, h1, l1, h2, l2, h3, l3;
            split2(v.x, h0, l0); split2(v.y, h1, l1);
            split2(v.z, h2, l2); split2(v.w, h3, l3);
            int o = k * LDA + c;
            Whi[o] = h0; Whi[o+1] = h1; Whi[o+2] = h2; Whi[o+3] = h3;
            Wlo[o] = l0; Wlo[o+1] = l1; Wlo[o+2] = l2; Wlo[o+3] = l3;
        }
    }

    // --- CSR pull gather: warp w owns rows 16w .. 16w+15 ---
    for (int t = 0; t < 16; ++t) {
        int r = wid * 16 + t;
        int node = row0 + r;
        float4 acc = make_float4(0.f, 0.f, 0.f, 0.f);
        if (node < n_nodes) {
            acc = X4[(size_t)node * D4 + lane];
            int s = g_rowstart[node];
            int e = s + g_deg[node];
            int j = s;
            for (; j + 4 <= e; j += 4) {
                int n0 = g_adj[j + 0], n1 = g_adj[j + 1];
                int n2 = g_adj[j + 2], n3 = g_adj[j + 3];
                float4 v0 = X4[(size_t)n0 * D4 + lane];
                float4 v1 = X4[(size_t)n1 * D4 + lane];
                float4 v2 = X4[(size_t)n2 * D4 + lane];
                float4 v3 = X4[(size_t)n3 * D4 + lane];
                acc.x += v0.x + v1.x + v2.x + v3.x;
                acc.y += v0.y + v1.y + v2.y + v3.y;
                acc.z += v0.z + v1.z + v2.z + v3.z;
                acc.w += v0.w + v1.w + v2.w + v3.w;
            }
            for (; j < e; ++j) {
                int nb = g_adj[j];
                float4 v = X4[(size_t)nb * D4 + lane];
                acc.x += v.x; acc.y += v.y; acc.z += v.z; acc.w += v.w;
            }
        }
        __nv_bfloat16 h0, l0, h1, l1, h2, l2, h3, l3;
        split2(acc.x, h0, l0); split2(acc.y, h1, l1);
        split2(acc.z, h2, l2); split2(acc.w, h3, l3);
        int o = r * LDA + lane * 4;
        Ahi[o] = h0; Ahi[o+1] = h1; Ahi[o+2] = h2; Ahi[o+3] = h3;
        Alo[o] = l0; Alo[o+1] = l1; Alo[o+2] = l2; Alo[o+3] = l3;
    }
    __syncthreads();

    typedef wmma::fragment<wmma::matrix_a, 16, 16, 16, __nv_bfloat16, wmma::row_major> FragA;
    typedef wmma::fragment<wmma::matrix_b, 16, 16, 16, __nv_bfloat16, wmma::row_major> FragB;
    typedef wmma::fragment<wmma::accumulator, 16, 16, 16, float> FragC;

    // ---------------- GEMM 1 ----------------
    {
        FragC acc[8];
        #pragma unroll
        for (int n = 0; n < 8; ++n) wmma::fill_fragment(acc[n], 0.f);
        for (int k = 0; k < 8; ++k) {
            FragA a_hi, a_lo;
            wmma::load_matrix_sync(a_hi, Ahi + wid * 16 * LDA + k * 16, LDA);
            wmma::load_matrix_sync(a_lo, Alo + wid * 16 * LDA + k * 16, LDA);
            #pragma unroll
            for (int n = 0; n < 8; ++n) {
                FragB b_hi, b_lo;
                wmma::load_matrix_sync(b_hi, Whi + k * 16 * LDA + n * 16, LDA);
                wmma::mma_sync(acc[n], a_hi, b_hi, acc[n]);
                wmma::mma_sync(acc[n], a_lo, b_hi, acc[n]);
                wmma::load_matrix_sync(b_lo, Wlo + k * 16 * LDA + n * 16, LDA);
                wmma::mma_sync(acc[n], a_hi, b_lo, acc[n]);
            }
        }
        #pragma unroll
        for (int n = 0; n < 8; ++n)
            wmma::store_matrix_sync(Hf + wid * 16 * LDH + n * 16, acc[n], LDH, wmma::mem_row_major);
    }
    __syncthreads();

    // --- bias + relu + re-split H; stage Wo over W buffers ---
    #pragma unroll
    for (int it = 0; it < 16; ++it) {
        int i = tid + it * 256;
        int r = i >> 5, c = (i & 31) * 4;
        float4 v = *(const float4*)&Hf[r * LDH + c];
        float x0 = fmaxf(v.x + bh_s[c + 0], 0.f);
        float x1 = fmaxf(v.y + bh_s[c + 1], 0.f);
        float x2 = fmaxf(v.z + bh_s[c + 2], 0.f);
        float x3 = fmaxf(v.w + bh_s[c + 3], 0.f);
        __nv_bfloat16 h0, l0, h1, l1, h2, l2, h3, l3;
        split2(x0, h0, l0); split2(x1, h1, l1);
        split2(x2, h2, l2); split2(x3, h3, l3);
        int o = r * LDA + c;
        Ahi[o] = h0; Ahi[o+1] = h1; Ahi[o+2] = h2; Ahi[o+3] = h3;
        Alo[o] = l0; Alo[o+1] = l1; Alo[o+2] = l2; Alo[o+3] = l3;
    }
    {
        const float4* W4 = (const float4*)Wo;
        #pragma unroll
        for (int it = 0; it < 16; ++it) {
            int i = tid + it * 256;
            int k = i >> 5, c = (i & 31) * 4;
            float4 v = W4[i];
            __nv_bfloat16 h0, l0, h1, l1, h2, l2, h3, l3;
            split2(v.x, h0, l0); split2(v.y, h1, l1);
            split2(v.z, h2, l2); split2(v.w, h3, l3);
            int o = k * LDA + c;
            Whi[o] = h0; Whi[o+1] = h1; Whi[o+2] = h2; Whi[o+3] = h3;
            Wlo[o] = l0; Wlo[o+1] = l1; Wlo[o+2] = l2; Wlo[o+3] = l3;
        }
    }
    __syncthreads();

    // ---------------- GEMM 2 ----------------
    {
        FragC acc[8];
        #pragma unroll
        for (int n = 0; n < 8; ++n) wmma::fill_fragment(acc[n], 0.f);
        for (int k = 0; k < 8; ++k) {
            FragA a_hi, a_lo;
            wmma::load_matrix_sync(a_hi, Ahi + wid * 16 * LDA + k * 16, LDA);
            wmma::load_matrix_sync(a_lo, Alo + wid * 16 * LDA + k * 16, LDA);
            #pragma unroll
            for (int n = 0; n < 8; ++n) {
                FragB b_hi, b_lo;
                wmma::load_matrix_sync(b_hi, Whi + k * 16 * LDA + n * 16, LDA);
                wmma::mma_sync(acc[n], a_hi, b_hi, acc[n]);
                wmma::mma_sync(acc[n], a_lo, b_hi, acc[n]);
                wmma::load_matrix_sync(b_lo, Wlo + k * 16 * LDA + n * 16, LDA);
                wmma::mma_sync(acc[n], a_hi, b_lo, acc[n]);
            }
        }
        #pragma unroll
        for (int n = 0; n < 8; ++n)
            wmma::store_matrix_sync(Hf + wid * 16 * LDH + n * 16, acc[n], LDH, wmma::mem_row_major);
    }
    __syncthreads();

    // --- final: out = Hf + bo ---
    #pragma unroll
    for (int it = 0; it < 16; ++it) {
        int i = tid + it * 256;
        int r = i >> 5, c = (i & 31) * 4;
        if (row0 + r < n_nodes) {
            float4 v = *(const float4*)&Hf[r * LDH + c];
            float4 o4;
            o4.x = v.x + bo_s[c + 0];
            o4.y = v.y + bo_s[c + 1];
            o4.z = v.z + bo_s[c + 2];
            o4.w = v.w + bo_s[c + 3];
            *(float4*)&out[(size_t)(row0 + r) * D + c] = o4;
        }
    }
}

// ===========================================================================
extern "C" void kernel_launch(void* const* d_in, const int* in_sizes, int n_in,
                              void* d_out, int out_size) {
    const float* X  = (const float*)d_in[0];
    const int*   ra = (const int*)  d_in[1];
    const int*   rb = (const int*)  d_in[2];
    const float* Wh = (const float*)d_in[3];
    const float* bh = (const float*)d_in[4];
    const float* Wo = (const float*)d_in[5];
    const float* bo = (const float*)d_in[6];
    float* out = (float*)d_out;

    const int n_nodes = in_sizes[0] / D;
    const int n_edges = in_sizes[1];
    const int nb = (n_nodes + 1023) / 1024;

    // --- CSR build (every replay) ---
    zero_deg_kernel<<<(n_nodes + 255) / 256, 256>>>(n_nodes);
    hist_kernel<<<(n_edges + 255) / 256, 256>>>(ra, rb, n_edges);
    scan_block_kernel<<<nb, 1024>>>(n_nodes);
    scan_top_kernel<<<1, 256>>>(nb);
    scan_add_kernel<<<nb, 1024>>>(n_nodes);
    fill_adj_kernel<<<(n_edges + 255) / 256, 256>>>(ra, rb, n_edges);

    // --- fused gather + two-layer tensor-core GEMM ---
    cudaFuncSetAttribute(fused_gather_wmma_kernel,
                         cudaFuncAttributeMaxDynamicSharedMemorySize, SM_TOTAL);
    int gblocks = (n_nodes + 127) / 128;
    fused_gather_wmma_kernel<<<gblocks, 256, SM_TOTAL>>>(
        (const float4*)X, Wh, bh, Wo, bo, out, n_nodes);
}

// round 7
// speedup vs baseline: 1.5954x; 1.5954x over previous
#include <cuda_runtime.h>
#include <cuda_bf16.h>
#include <mma.h>
#include <cstdint>

using namespace nvcuda;

#define MAX_NODES 100032
#define MAX_EDGES 700000
#define D 128
#define D4 (D / 4)

// CSR scratch (rebuilt every replay) + aggregated features
__device__ int g_deg[MAX_NODES];
__device__ int g_rowstart[MAX_NODES];
__device__ int g_cursor[MAX_NODES];
__device__ int g_bsum[256];
__device__ int g_adj[2 * MAX_EDGES];
__device__ float g_agg[(size_t)MAX_NODES * D];

// ===========================================================================
// CSR build
// ===========================================================================
__global__ void zero_deg_kernel(int n) {
    int i = blockIdx.x * blockDim.x + threadIdx.x;
    if (i < n) g_deg[i] = 0;
}

__global__ void hist_kernel(const int* __restrict__ ra, const int* __restrict__ rb, int n_edges) {
    int e = blockIdx.x * blockDim.x + threadIdx.x;
    if (e >= n_edges) return;
    atomicAdd(&g_deg[ra[e]], 1);
    atomicAdd(&g_deg[rb[e]], 1);
}

__global__ void scan_block_kernel(int n) {
    __shared__ int wsum[32];
    int i = blockIdx.x * 1024 + threadIdx.x;
    int lane = threadIdx.x & 31, w = threadIdx.x >> 5;
    int v = (i < n) ? g_deg[i] : 0;
    int s = v;
    #pragma unroll
    for (int o = 1; o < 32; o <<= 1) {
        int t = __shfl_up_sync(0xFFFFFFFFu, s, o);
        if (lane >= o) s += t;
    }
    if (lane == 31) wsum[w] = s;
    __syncthreads();
    if (threadIdx.x < 32) {
        int t = wsum[threadIdx.x];
        int sc = t;
        #pragma unroll
        for (int o = 1; o < 32; o <<= 1) {
            int u = __shfl_up_sync(0xFFFFFFFFu, sc, o);
            if (lane >= o) sc += u;
        }
        wsum[threadIdx.x] = sc - t;
        if (threadIdx.x == 31) g_bsum[blockIdx.x] = sc;
    }
    __syncthreads();
    if (i < n) g_rowstart[i] = (s - v) + wsum[w];
}

// parallel Hillis-Steele scan over <=256 block sums (replaces serial loop)
__global__ void scan_top_kernel(int nb) {
    __shared__ int sm[256];
    int t = threadIdx.x;
    int v = (t < nb) ? g_bsum[t] : 0;
    sm[t] = v;
    __syncthreads();
    #pragma unroll
    for (int o = 1; o < 256; o <<= 1) {
        int u = (t >= o) ? sm[t - o] : 0;
        __syncthreads();
        sm[t] += u;
        __syncthreads();
    }
    if (t < nb) g_bsum[t] = sm[t] - v;   // exclusive
}

__global__ void scan_add_kernel(int n) {
    int i = blockIdx.x * 1024 + threadIdx.x;
    if (i < n) {
        int rs = g_rowstart[i] + g_bsum[blockIdx.x];
        g_rowstart[i] = rs;
        g_cursor[i] = rs;
    }
}

__global__ void fill_adj_kernel(const int* __restrict__ ra, const int* __restrict__ rb, int n_edges) {
    int e = blockIdx.x * blockDim.x + threadIdx.x;
    if (e >= n_edges) return;
    int a = ra[e], b = rb[e];
    int p = atomicAdd(&g_cursor[a], 1);
    g_adj[p] = b;
    int q = atomicAdd(&g_cursor[b], 1);
    g_adj[q] = a;
}

// ===========================================================================
// Pull gather: warp-per-node, full occupancy. agg[v] = X[v] + sum_nbr X[u].
// ===========================================================================
__global__ __launch_bounds__(256)
void gather_kernel(const float4* __restrict__ X4, float4* __restrict__ agg4, int n_nodes) {
    int warp = (blockIdx.x * blockDim.x + threadIdx.x) >> 5;
    int lane = threadIdx.x & 31;
    if (warp >= n_nodes) return;

    float4 acc = X4[(size_t)warp * D4 + lane];
    int s = g_rowstart[warp];
    int e = s + g_deg[warp];
    int j = s;
    for (; j + 4 <= e; j += 4) {
        int n0 = g_adj[j + 0], n1 = g_adj[j + 1];
        int n2 = g_adj[j + 2], n3 = g_adj[j + 3];
        float4 v0 = X4[(size_t)n0 * D4 + lane];
        float4 v1 = X4[(size_t)n1 * D4 + lane];
        float4 v2 = X4[(size_t)n2 * D4 + lane];
        float4 v3 = X4[(size_t)n3 * D4 + lane];
        acc.x += (v0.x + v1.x) + (v2.x + v3.x);
        acc.y += (v0.y + v1.y) + (v2.y + v3.y);
        acc.z += (v0.z + v1.z) + (v2.z + v3.z);
        acc.w += (v0.w + v1.w) + (v2.w + v3.w);
    }
    for (; j < e; ++j) {
        int nb = g_adj[j];
        float4 v = X4[(size_t)nb * D4 + lane];
        acc.x += v.x; acc.y += v.y; acc.z += v.z; acc.w += v.w;
    }
    agg4[(size_t)warp * D4 + lane] = acc;
}

// ===========================================================================
// Fused 2-layer GEMM, bf16x3 split, wmma. 512 threads / 16 warps.
// Warp tile 16 rows x 64 cols: wr = wid>>1, wc = wid&1.
// ===========================================================================
#define LDA 136
#define LDH 132

#define SM_BH  0
#define SM_BO  512
#define SM_AHI 1024
#define SM_ALO (SM_AHI + 128 * LDA * 2)
#define SM_WHI (SM_ALO + 128 * LDA * 2)
#define SM_WLO (SM_WHI + 128 * LDA * 2)
#define SM_HF  (SM_WLO + 128 * LDA * 2)
#define SM_TOTAL (SM_HF + 128 * LDH * 4)   // 207872 bytes

__device__ __forceinline__ void split2(float x, __nv_bfloat16& hi, __nv_bfloat16& lo) {
    hi = __float2bfloat16_rn(x);
    lo = __float2bfloat16_rn(x - __bfloat162float(hi));
}

__global__ __launch_bounds__(512, 1)
void fused_wmma_kernel(const float* __restrict__ Wh, const float* __restrict__ bh,
                       const float* __restrict__ Wo, const float* __restrict__ bo,
                       float* __restrict__ out, int n_nodes) {
    extern __shared__ char smem[];
    float*          bh_s = (float*)(smem + SM_BH);
    float*          bo_s = (float*)(smem + SM_BO);
    __nv_bfloat16*  Ahi  = (__nv_bfloat16*)(smem + SM_AHI);
    __nv_bfloat16*  Alo  = (__nv_bfloat16*)(smem + SM_ALO);
    __nv_bfloat16*  Whi  = (__nv_bfloat16*)(smem + SM_WHI);
    __nv_bfloat16*  Wlo  = (__nv_bfloat16*)(smem + SM_WLO);
    float*          Hf   = (float*)(smem + SM_HF);

    const int tid = threadIdx.x;
    const int wid = tid >> 5;
    const int row0 = blockIdx.x * 128;

    if (tid < 128) bh_s[tid] = bh[tid];
    else if (tid < 256) bo_s[tid - 128] = bo[tid - 128];

    // --- stage A tile (hi/lo split) ---
    const float4* agg4 = (const float4*)g_agg;
    #pragma unroll
    for (int it = 0; it < 8; ++it) {
        int i = tid + it * 512;            // 4096 float4 slots = 128r x 32q
        int r = i >> 5, c = (i & 31) * 4;
        float4 v = make_float4(0.f, 0.f, 0.f, 0.f);
        if (row0 + r < n_nodes) v = agg4[(size_t)(row0 + r) * D4 + (c >> 2)];
        __nv_bfloat16 h0, l0, h1, l1, h2, l2, h3, l3;
        split2(v.x, h0, l0); split2(v.y, h1, l1);
        split2(v.z, h2, l2); split2(v.w, h3, l3);
        int o = r * LDA + c;
        Ahi[o] = h0; Ahi[o+1] = h1; Ahi[o+2] = h2; Ahi[o+3] = h3;
        Alo[o] = l0; Alo[o+1] = l1; Alo[o+2] = l2; Alo[o+3] = l3;
    }
    // --- stage Wh ---
    {
        const float4* W4 = (const float4*)Wh;
        #pragma unroll
        for (int it = 0; it < 8; ++it) {
            int i = tid + it * 512;
            int k = i >> 5, c = (i & 31) * 4;
            float4 v = W4[i];
            __nv_bfloat16 h0, l0, h1, l1, h2, l2, h3, l3;
            split2(v.x, h0, l0); split2(v.y, h1, l1);
            split2(v.z, h2, l2); split2(v.w, h3, l3);
            int o = k * LDA + c;
            Whi[o] = h0; Whi[o+1] = h1; Whi[o+2] = h2; Whi[o+3] = h3;
            Wlo[o] = l0; Wlo[o+1] = l1; Wlo[o+2] = l2; Wlo[o+3] = l3;
        }
    }
    __syncthreads();

    typedef wmma::fragment<wmma::matrix_a, 16, 16, 16, __nv_bfloat16, wmma::row_major> FragA;
    typedef wmma::fragment<wmma::matrix_b, 16, 16, 16, __nv_bfloat16, wmma::row_major> FragB;
    typedef wmma::fragment<wmma::accumulator, 16, 16, 16, float> FragC;

    const int wr = wid >> 1;       // row block 0..7
    const int wc = wid & 1;        // col half 0..1

    // ---------------- GEMM 1 ----------------
    {
        FragC acc[4];
        #pragma unroll
        for (int n = 0; n < 4; ++n) wmma::fill_fragment(acc[n], 0.f);
        for (int k = 0; k < 8; ++k) {
            FragA a_hi, a_lo;
            wmma::load_matrix_sync(a_hi, Ahi + wr * 16 * LDA + k * 16, LDA);
            wmma::load_matrix_sync(a_lo, Alo + wr * 16 * LDA + k * 16, LDA);
            #pragma unroll
            for (int n = 0; n < 4; ++n) {
                int nc = wc * 64 + n * 16;
                FragB b_hi, b_lo;
                wmma::load_matrix_sync(b_hi, Whi + k * 16 * LDA + nc, LDA);
                wmma::mma_sync(acc[n], a_hi, b_hi, acc[n]);
                wmma::mma_sync(acc[n], a_lo, b_hi, acc[n]);
                wmma::load_matrix_sync(b_lo, Wlo + k * 16 * LDA + nc, LDA);
                wmma::mma_sync(acc[n], a_hi, b_lo, acc[n]);
            }
        }
        #pragma unroll
        for (int n = 0; n < 4; ++n)
            wmma::store_matrix_sync(Hf + wr * 16 * LDH + wc * 64 + n * 16, acc[n], LDH, wmma::mem_row_major);
    }
    __syncthreads();

    // --- bias + relu + re-split H; stage Wo ---
    #pragma unroll
    for (int it = 0; it < 8; ++it) {
        int i = tid + it * 512;
        int r = i >> 5, c = (i & 31) * 4;
        float4 v = *(const float4*)&Hf[r * LDH + c];
        float x0 = fmaxf(v.x + bh_s[c + 0], 0.f);
        float x1 = fmaxf(v.y + bh_s[c + 1], 0.f);
        float x2 = fmaxf(v.z + bh_s[c + 2], 0.f);
        float x3 = fmaxf(v.w + bh_s[c + 3], 0.f);
        __nv_bfloat16 h0, l0, h1, l1, h2, l2, h3, l3;
        split2(x0, h0, l0); split2(x1, h1, l1);
        split2(x2, h2, l2); split2(x3, h3, l3);
        int o = r * LDA + c;
        Ahi[o] = h0; Ahi[o+1] = h1; Ahi[o+2] = h2; Ahi[o+3] = h3;
        Alo[o] = l0; Alo[o+1] = l1; Alo[o+2] = l2; Alo[o+3] = l3;
    }
    {
        const float4* W4 = (const float4*)Wo;
        #pragma unroll
        for (int it = 0; it < 8; ++it) {
            int i = tid + it * 512;
            int k = i >> 5, c = (i & 31) * 4;
            float4 v = W4[i];
            __nv_bfloat16 h0, l0, h1, l1, h2, l2, h3, l3;
            split2(v.x, h0, l0); split2(v.y, h1, l1);
            split2(v.z, h2, l2); split2(v.w, h3, l3);
            int o = k * LDA + c;
            Whi[o] = h0; Whi[o+1] = h1; Whi[o+2] = h2; Whi[o+3] = h3;
            Wlo[o] = l0; Wlo[o+1] = l1; Wlo[o+2] = l2; Wlo[o+3] = l3;
        }
    }
    __syncthreads();

    // ---------------- GEMM 2 ----------------
    {
        FragC acc[4];
        #pragma unroll
        for (int n = 0; n < 4; ++n) wmma::fill_fragment(acc[n], 0.f);
        for (int k = 0; k < 8; ++k) {
            FragA a_hi, a_lo;
            wmma::load_matrix_sync(a_hi, Ahi + wr * 16 * LDA + k * 16, LDA);
            wmma::load_matrix_sync(a_lo, Alo + wr * 16 * LDA + k * 16, LDA);
            #pragma unroll
            for (int n = 0; n < 4; ++n) {
                int nc = wc * 64 + n * 16;
                FragB b_hi, b_lo;
                wmma::load_matrix_sync(b_hi, Whi + k * 16 * LDA + nc, LDA);
                wmma::mma_sync(acc[n], a_hi, b_hi, acc[n]);
                wmma::mma_sync(acc[n], a_lo, b_hi, acc[n]);
                wmma::load_matrix_sync(b_lo, Wlo + k * 16 * LDA + nc, LDA);
                wmma::mma_sync(acc[n], a_hi, b_lo, acc[n]);
            }
        }
        #pragma unroll
        for (int n = 0; n < 4; ++n)
            wmma::store_matrix_sync(Hf + wr * 16 * LDH + wc * 64 + n * 16, acc[n], LDH, wmma::mem_row_major);
    }
    __syncthreads();

    // --- final: out = Hf + bo ---
    #pragma unroll
    for (int it = 0; it < 8; ++it) {
        int i = tid + it * 512;
        int r = i >> 5, c = (i & 31) * 4;
        if (row0 + r < n_nodes) {
            float4 v = *(const float4*)&Hf[r * LDH + c];
            float4 o4;
            o4.x = v.x + bo_s[c + 0];
            o4.y = v.y + bo_s[c + 1];
            o4.z = v.z + bo_s[c + 2];
            o4.w = v.w + bo_s[c + 3];
            *(float4*)&out[(size_t)(row0 + r) * D + c] = o4;
        }
    }
}

// ===========================================================================
extern "C" void kernel_launch(void* const* d_in, const int* in_sizes, int n_in,
                              void* d_out, int out_size) {
    const float* X  = (const float*)d_in[0];
    const int*   ra = (const int*)  d_in[1];
    const int*   rb = (const int*)  d_in[2];
    const float* Wh = (const float*)d_in[3];
    const float* bh = (const float*)d_in[4];
    const float* Wo = (const float*)d_in[5];
    const float* bo = (const float*)d_in[6];
    float* out = (float*)d_out;

    const int n_nodes = in_sizes[0] / D;
    const int n_edges = in_sizes[1];
    const int nb = (n_nodes + 1023) / 1024;

    float* agg;
    cudaGetSymbolAddress((void**)&agg, g_agg);

    // --- CSR build ---
    zero_deg_kernel<<<(n_nodes + 255) / 256, 256>>>(n_nodes);
    hist_kernel<<<(n_edges + 255) / 256, 256>>>(ra, rb, n_edges);
    scan_block_kernel<<<nb, 1024>>>(n_nodes);
    scan_top_kernel<<<1, 256>>>(nb);
    scan_add_kernel<<<nb, 1024>>>(n_nodes);
    fill_adj_kernel<<<(n_edges + 255) / 256, 256>>>(ra, rb, n_edges);

    // --- pull gather (warp-per-node, high occupancy) ---
    int gwarps = (n_nodes * 32 + 255) / 256;
    gather_kernel<<<gwarps, 256>>>((const float4*)X, (float4*)agg, n_nodes);

    // --- fused two-layer tensor-core GEMM ---
    cudaFuncSetAttribute(fused_wmma_kernel,
                         cudaFuncAttributeMaxDynamicSharedMemorySize, SM_TOTAL);
    int gblocks = (n_nodes + 127) / 128;
    fused_wmma_kernel<<<gblocks, 512, SM_TOTAL>>>(Wh, bh, Wo, bo, out, n_nodes);
}